// round 14
// baseline (speedup 1.0000x reference)
#include <cuda_runtime.h>
#include <cuda_bf16.h>

// Problem shape (fixed by the dataset)
#define N_DIM 8
#define V_DIM 3
#define C_DIM 24
#define T_DIM 8
#define H_DIM 128
#define W_DIM 128

constexpr int HW      = H_DIM * W_DIM;         // 16384
constexpr int VCT     = V_DIM * C_DIM * T_DIM; // 576 slabs per n
constexpr int CHUNK   = 2048;                  // hw positions per block
constexpr int NCHUNK  = HW / CHUNK;            // 8
constexpr int GROUP   = 64;                    // slabs per block (8 c x 8 t, within one v)
constexpr int NGROUP  = VCT / GROUP;           // 9
constexpr int MAIN_BLOCKS = N_DIM * NCHUNK * NGROUP;  // 576: ONE wave at 4/SM
constexpr int THREADS = 256;

// Deterministic reduction scratch (static device globals — no allocation)
__device__ float g_part[MAIN_BLOCKS];
__device__ float g_maskchunk[N_DIM * NCHUNK];   // per-(n,chunk) integer mask sums (exact)
__device__ unsigned int g_count = 0;            // completion counter (reset by finisher)

// st.global.cg — write straight to L2
__device__ __forceinline__ void stcg(float* p, float v) {
    asm volatile("st.global.cg.f32 [%0], %1;" :: "l"(p), "f"(v) : "memory");
}
__device__ __forceinline__ float ldcg(const float* p) {
    float v;
    asm volatile("ld.global.cg.f32 %0, [%1];" : "=f"(v) : "l"(p) : "memory");
    return v;
}
// acq_rel gpu-scope atomic add (sem/scope BEFORE space per PTX grammar).
// Release orders our prior partial store; acquire orders the finisher's loads.
__device__ __forceinline__ unsigned int atomic_add_acqrel(unsigned int* p, unsigned int v) {
    unsigned int old;
    asm volatile("atom.acq_rel.gpu.global.add.u32 %0, [%1], %2;"
                 : "=r"(old) : "l"(p), "r"(v) : "memory");
    return old;
}

__global__ __launch_bounds__(THREADS, 4)     // 64-reg budget: no spills, 4 blocks/SM
void anomaly_l1_fused(const float* __restrict__ pred,
                      const int*   __restrict__ mask,
                      const float* __restrict__ vq0,
                      float* __restrict__ out)
{
    __shared__ float sred[THREADS / 32];
    __shared__ unsigned int s_isLast;

    const int b   = blockIdx.x;
    const int tid = threadIdx.x;

    // ---- decode (n, chunk, group) ----
    const int group = b % NGROUP;                  // 0..8
    const int chunk = (b / NGROUP) % NCHUNK;       // 0..7
    const int n     = b / (NGROUP * NCHUNK);       // 0..7

    // Weights in REGISTERS: this thread touches the same 8 hw positions in all
    // 64 of its slabs. 8 regs; no SMEM staging, no LDS in the hot loop.
    float4 w0, w1;
    int msum_local;
    {
        const int4* m4 = reinterpret_cast<const int4*>(mask + n * HW + chunk * CHUNK);
        int4 a = __ldcs(&m4[tid]);                 // single-use: evict-first
        int4 c = __ldcs(&m4[tid + THREADS]);
        msum_local = a.x + a.y + a.z + a.w + c.x + c.y + c.z + c.w;
        w0 = make_float4(1.f - (float)a.x, 1.f - (float)a.y,
                         1.f - (float)a.z, 1.f - (float)a.w);
        w1 = make_float4(1.f - (float)c.x, 1.f - (float)c.y,
                         1.f - (float)c.z, 1.f - (float)c.w);
    }

    // group==0 blocks record their (n,chunk) mask sum (integer adds: exact,
    // order-independent → exact denominator).
    if (group == 0) {
        int s = msum_local;
        #pragma unroll
        for (int o = 16; o; o >>= 1) s += __shfl_xor_sync(0xFFFFFFFFu, s, o);
        if ((tid & 31) == 0) sred[tid >> 5] = (float)s;
        __syncthreads();
        if (tid == 0) {
            float t = 0.f;
            #pragma unroll
            for (int i = 0; i < THREADS / 32; ++i) t += sred[i];  // ints <= 2048: exact
            stcg(&g_maskchunk[n * NCHUNK + chunk], t);
        }
        __syncthreads();   // sred reused below
    }

    // Slabs group*64 .. group*64+63: c = (group%3)*8 + j (j=0..7), t = 0..7.
    // 64*3 = 192 = one v-extent, so no v boundary is crossed.
    const int c0 = (group % 3) * 8;
    const float* base = pred + ((size_t)n * VCT + (size_t)group * GROUP) * (size_t)HW
                             + (size_t)chunk * CHUNK;

    float acc0 = 0.f, acc1 = 0.f;     // two independent FMA chains
    #pragma unroll 1
    for (int j = 0; j < 8; ++j) {                  // 8 c-values
        const float vq = __ldg(vq0 + c0 + j);      // L1-resident
        const float* jb = base + (size_t)(j * 8) * HW;
        #pragma unroll 1
        for (int th = 0; th < 2; ++th) {           // 2 half-batches of 4 t
            const float* tb = jb + (size_t)(th * 4) * HW;
            #pragma unroll
            for (int t = 0; t < 4; ++t) {          // 8 batched LDG.128 (32 data regs)
                const float4* p = reinterpret_cast<const float4*>(tb + (size_t)t * HW);
                float4 x0 = __ldcs(&p[tid]);            // streaming: evict-first L1+L2
                float4 x1 = __ldcs(&p[tid + THREADS]);
                acc0 = fmaf(fabsf(x0.x - vq), w0.x, acc0);
                acc0 = fmaf(fabsf(x0.y - vq), w0.y, acc0);
                acc0 = fmaf(fabsf(x0.z - vq), w0.z, acc0);
                acc0 = fmaf(fabsf(x0.w - vq), w0.w, acc0);
                acc1 = fmaf(fabsf(x1.x - vq), w1.x, acc1);
                acc1 = fmaf(fabsf(x1.y - vq), w1.y, acc1);
                acc1 = fmaf(fabsf(x1.z - vq), w1.z, acc1);
                acc1 = fmaf(fabsf(x1.w - vq), w1.w, acc1);
            }
        }
    }

    float acc = acc0 + acc1;
    #pragma unroll
    for (int o = 16; o; o >>= 1) acc += __shfl_xor_sync(0xFFFFFFFFu, acc, o);
    if ((tid & 31) == 0) sred[tid >> 5] = acc;
    __syncthreads();
    if (tid == 0) {
        float t = 0.f;
        #pragma unroll
        for (int i = 0; i < THREADS / 32; ++i) t += sred[i];
        stcg(&g_part[b], t);
        // Release-ordered completion mark (elects the finisher).
        unsigned int prev = atomic_add_acqrel(&g_count, 1u);
        s_isLast = (prev == MAIN_BLOCKS - 1u) ? 1u : 0u;
    }
    __syncthreads();

    // ---- last-block-finishes: deterministic final reduction ----
    // Summation walks g_part[] in fixed index order → bit-deterministic.
    if (s_isLast) {
        float a = 0.f;
        #pragma unroll 1
        for (int i = tid; i < MAIN_BLOCKS; i += THREADS) a += ldcg(&g_part[i]);
        #pragma unroll
        for (int o = 16; o; o >>= 1) a += __shfl_xor_sync(0xFFFFFFFFu, a, o);
        if ((tid & 31) == 0) sred[tid >> 5] = a;
        __syncthreads();
        if (tid == 0) {
            float num = 0.f;
            #pragma unroll
            for (int i = 0; i < THREADS / 32; ++i) num += sred[i];
            float msum = 0.f;
            #pragma unroll
            for (int i = 0; i < N_DIM * NCHUNK; ++i) msum += ldcg(&g_maskchunk[i]);
            double sumw = (double)N_DIM * HW - (double)msum;  // sum of weights over (N,H,W)
            double den  = sumw * (double)VCT;
            out[0] = (float)((double)num / den);
            g_count = 0;   // reset for next graph replay
        }
    }
}

extern "C" void kernel_launch(void* const* d_in, const int* in_sizes, int n_in,
                              void* d_out, int out_size)
{
    const float* pred = (const float*)d_in[0];   // (N,V,C,T,H,W) fp32
    const int*   mask = (const int*)  d_in[1];   // (N,H,W) int32
    const float* vq0  = (const float*)d_in[2];   // (1,C) fp32
    float* out = (float*)d_out;

    anomaly_l1_fused<<<MAIN_BLOCKS, THREADS>>>(pred, mask, vq0, out);
}

// round 15
// speedup vs baseline: 1.0303x; 1.0303x over previous
#include <cuda_runtime.h>
#include <cuda_bf16.h>

// Problem shape (fixed by the dataset)
#define N_DIM 8
#define V_DIM 3
#define C_DIM 24
#define T_DIM 8
#define H_DIM 128
#define W_DIM 128

constexpr int HW      = H_DIM * W_DIM;         // 16384
constexpr int VCT     = V_DIM * C_DIM * T_DIM; // 576 slabs per n
constexpr int CHUNK   = 2048;                  // hw positions per block
constexpr int NCHUNK  = HW / CHUNK;            // 8
constexpr int GROUP   = 64;                    // slabs per block (8 c x 8 t, within one v)
constexpr int NGROUP  = VCT / GROUP;           // 9
constexpr int MAIN_BLOCKS = N_DIM * NCHUNK * NGROUP;  // 576: ONE wave at 4/SM
constexpr int THREADS = 256;

// Deterministic reduction scratch (static device globals — no allocation)
__device__ float g_part[MAIN_BLOCKS];
__device__ float g_maskchunk[N_DIM * NCHUNK];   // per-(n,chunk) integer mask sums (exact)
__device__ unsigned int g_count = 0;            // completion counter (reset by finisher)

// st.global.cg — write straight to L2
__device__ __forceinline__ void stcg(float* p, float v) {
    asm volatile("st.global.cg.f32 [%0], %1;" :: "l"(p), "f"(v) : "memory");
}
__device__ __forceinline__ float ldcg(const float* p) {
    float v;
    asm volatile("ld.global.cg.f32 %0, [%1];" : "=f"(v) : "l"(p) : "memory");
    return v;
}
// acq_rel gpu-scope atomic add (sem/scope BEFORE space per PTX grammar).
// Release orders our prior partial store; acquire orders the finisher's loads.
__device__ __forceinline__ unsigned int atomic_add_acqrel(unsigned int* p, unsigned int v) {
    unsigned int old;
    asm volatile("atom.acq_rel.gpu.global.add.u32 %0, [%1], %2;"
                 : "=r"(old) : "l"(p), "r"(v) : "memory");
    return old;
}

__global__ __launch_bounds__(THREADS, 4)     // 64-reg budget: no spills, 4 blocks/SM
void anomaly_l1_fused(const float* __restrict__ pred,
                      const int*   __restrict__ mask,
                      const float* __restrict__ vq0,
                      float* __restrict__ out)
{
    __shared__ float sred[THREADS / 32];
    __shared__ unsigned int s_isLast;

    const int b   = blockIdx.x;
    const int tid = threadIdx.x;

    // ---- decode (n, chunk, group) ----
    const int group = b % NGROUP;                  // 0..8
    const int chunk = (b / NGROUP) % NCHUNK;       // 0..7
    const int n     = b / (NGROUP * NCHUNK);       // 0..7

    // Weights in REGISTERS: this thread touches the same 8 hw positions in all
    // 64 of its slabs. 8 regs; no SMEM staging, no LDS in the hot loop.
    float4 w0, w1;
    int msum_local;
    {
        const int4* m4 = reinterpret_cast<const int4*>(mask + n * HW + chunk * CHUNK);
        int4 a = m4[tid];
        int4 c = m4[tid + THREADS];
        msum_local = a.x + a.y + a.z + a.w + c.x + c.y + c.z + c.w;
        w0 = make_float4(1.f - (float)a.x, 1.f - (float)a.y,
                         1.f - (float)a.z, 1.f - (float)a.w);
        w1 = make_float4(1.f - (float)c.x, 1.f - (float)c.y,
                         1.f - (float)c.z, 1.f - (float)c.w);
    }

    // group==0 blocks record their (n,chunk) mask sum (integer adds: exact,
    // order-independent → exact denominator).
    if (group == 0) {
        int s = msum_local;
        #pragma unroll
        for (int o = 16; o; o >>= 1) s += __shfl_xor_sync(0xFFFFFFFFu, s, o);
        if ((tid & 31) == 0) sred[tid >> 5] = (float)s;
        __syncthreads();
        if (tid == 0) {
            float t = 0.f;
            #pragma unroll
            for (int i = 0; i < THREADS / 32; ++i) t += sred[i];  // ints <= 2048: exact
            stcg(&g_maskchunk[n * NCHUNK + chunk], t);
        }
        __syncthreads();   // sred reused below
    }

    // Slabs group*64 .. group*64+63: c = (group%3)*8 + j (j=0..7), t = 0..7.
    // 64*3 = 192 = one v-extent, so no v boundary is crossed.
    const int c0 = (group % 3) * 8;
    const float* base = pred + ((size_t)n * VCT + (size_t)group * GROUP) * (size_t)HW
                             + (size_t)chunk * CHUNK;

    float acc0 = 0.f, acc1 = 0.f;     // two independent FMA chains
    #pragma unroll 1
    for (int j = 0; j < 8; ++j) {                  // 8 c-values
        const float vq = __ldg(vq0 + c0 + j);      // L1-resident
        const float* jb = base + (size_t)(j * 8) * HW;
        #pragma unroll 1
        for (int th = 0; th < 2; ++th) {           // 2 half-batches of 4 t
            const float* tb = jb + (size_t)(th * 4) * HW;
            #pragma unroll
            for (int t = 0; t < 4; ++t) {          // 8 batched LDG.128 (32 data regs)
                const float4* p = reinterpret_cast<const float4*>(tb + (size_t)t * HW);
                float4 x0 = p[tid];
                float4 x1 = p[tid + THREADS];
                acc0 = fmaf(fabsf(x0.x - vq), w0.x, acc0);
                acc0 = fmaf(fabsf(x0.y - vq), w0.y, acc0);
                acc0 = fmaf(fabsf(x0.z - vq), w0.z, acc0);
                acc0 = fmaf(fabsf(x0.w - vq), w0.w, acc0);
                acc1 = fmaf(fabsf(x1.x - vq), w1.x, acc1);
                acc1 = fmaf(fabsf(x1.y - vq), w1.y, acc1);
                acc1 = fmaf(fabsf(x1.z - vq), w1.z, acc1);
                acc1 = fmaf(fabsf(x1.w - vq), w1.w, acc1);
            }
        }
    }

    float acc = acc0 + acc1;
    #pragma unroll
    for (int o = 16; o; o >>= 1) acc += __shfl_xor_sync(0xFFFFFFFFu, acc, o);
    if ((tid & 31) == 0) sred[tid >> 5] = acc;
    __syncthreads();
    if (tid == 0) {
        float t = 0.f;
        #pragma unroll
        for (int i = 0; i < THREADS / 32; ++i) t += sred[i];
        stcg(&g_part[b], t);
        // Release-ordered completion mark (elects the finisher).
        unsigned int prev = atomic_add_acqrel(&g_count, 1u);
        s_isLast = (prev == MAIN_BLOCKS - 1u) ? 1u : 0u;
    }
    __syncthreads();

    // ---- last-block-finishes: deterministic final reduction ----
    // Summation walks g_part[] in fixed index order → bit-deterministic.
    if (s_isLast) {
        float a = 0.f;
        #pragma unroll 1
        for (int i = tid; i < MAIN_BLOCKS; i += THREADS) a += ldcg(&g_part[i]);
        #pragma unroll
        for (int o = 16; o; o >>= 1) a += __shfl_xor_sync(0xFFFFFFFFu, a, o);
        if ((tid & 31) == 0) sred[tid >> 5] = a;
        __syncthreads();
        if (tid == 0) {
            float num = 0.f;
            #pragma unroll
            for (int i = 0; i < THREADS / 32; ++i) num += sred[i];
            float msum = 0.f;
            #pragma unroll
            for (int i = 0; i < N_DIM * NCHUNK; ++i) msum += ldcg(&g_maskchunk[i]);
            double sumw = (double)N_DIM * HW - (double)msum;  // sum of weights over (N,H,W)
            double den  = sumw * (double)VCT;
            out[0] = (float)((double)num / den);
            g_count = 0;   // reset for next graph replay
        }
    }
}

extern "C" void kernel_launch(void* const* d_in, const int* in_sizes, int n_in,
                              void* d_out, int out_size)
{
    const float* pred = (const float*)d_in[0];   // (N,V,C,T,H,W) fp32
    const int*   mask = (const int*)  d_in[1];   // (N,H,W) int32
    const float* vq0  = (const float*)d_in[2];   // (1,C) fp32
    float* out = (float*)d_out;

    anomaly_l1_fused<<<MAIN_BLOCKS, THREADS>>>(pred, mask, vq0, out);
}